// round 4
// baseline (speedup 1.0000x reference)
#include <cuda_runtime.h>
#include <math_constants.h>

#define N_NODES 50000
#define N_EDGES 800000
#define DIM 64
#define NCHUNK 98          // 98*512 = 50176 >= 50000
#define NTILES 782         // ceil(50000/64)

// ---- device scratch (no allocations allowed; static zero-init) ----
__device__ int   g_counts[N_NODES];      // invariant: zero at kernel entry, re-zeroed each run
__device__ int   g_offsets[N_NODES + 1];
__device__ int   g_cursor[N_NODES];
__device__ int   g_bsum[NCHUNK];
__device__ int   g_srcidx[N_EDGES];
__device__ float g_h0[N_NODES * DIM];
__device__ float g_h1[N_NODES * DIM];

// ---- software grid barrier (all blocks co-resident by construction) ----
__device__ volatile unsigned g_bar_gen = 0;
__device__ unsigned g_bar_cnt = 0;

__device__ __forceinline__ void grid_bar() {
    __syncthreads();
    if (threadIdx.x == 0) {
        __threadfence();
        unsigned g = g_bar_gen;
        if (atomicAdd(&g_bar_cnt, 1u) == gridDim.x - 1) {
            atomicExch(&g_bar_cnt, 0u);     // reset before release (release-acquire chain)
            __threadfence();
            g_bar_gen = g + 1;
        } else {
            while (g_bar_gen == g) __nanosleep(64);
            __threadfence();
        }
    }
    __syncthreads();
}

// ---------------- the whole GIN in one persistent kernel ----------------
__global__ void __launch_bounds__(512, 2) k_gin_all(
        const float* __restrict__ n_feat,
        const float* __restrict__ W0, const float* __restrict__ b0,
        const float* __restrict__ W1, const float* __restrict__ b1,
        const float* __restrict__ W2, const float* __restrict__ b2,
        const float* __restrict__ eps,
        const int*   __restrict__ src,
        const int*   __restrict__ dst,
        float* __restrict__ out) {
    __shared__ float Ws[64 * 64];     // [k][j]
    __shared__ float Xs[64 * 68];     // padded stride 68
    __shared__ int   warp_sums[16];
    __shared__ int   prefix_s;

    const int t    = threadIdx.x;     // 0..511
    const int lane = t & 31;
    const int wid  = t >> 5;
    const int gsz  = gridDim.x * 512;

    // ===== phase A: degree count (counts pre-zeroed) =====
    for (int i = blockIdx.x * 512 + t; i < N_EDGES / 4; i += gsz) {
        int4 d = __ldg((const int4*)dst + i);
        atomicAdd(&g_counts[d.x], 1);     // no return use -> RED
        atomicAdd(&g_counts[d.y], 1);
        atomicAdd(&g_counts[d.z], 1);
        atomicAdd(&g_counts[d.w], 1);
    }
    grid_bar();

    // ===== phase B1: per-chunk exclusive scan (512-wide chunks) =====
    for (int c = blockIdx.x; c < NCHUNK; c += gridDim.x) {
        int i = c * 512 + t;
        int v = (i < N_NODES) ? g_counts[i] : 0;
        int s = v;
        #pragma unroll
        for (int d = 1; d < 32; d <<= 1) {
            int y = __shfl_up_sync(0xffffffffu, s, d);
            if (lane >= d) s += y;
        }
        if (lane == 31) warp_sums[wid] = s;
        __syncthreads();
        if (wid == 0 && lane < 16) {
            int ws = warp_sums[lane];
            #pragma unroll
            for (int d = 1; d < 16; d <<= 1) {
                int y = __shfl_up_sync(0xffffu, ws, d);
                if (lane >= d) ws += y;
            }
            warp_sums[lane] = ws;
        }
        __syncthreads();
        int excl = s - v + (wid > 0 ? warp_sums[wid - 1] : 0);
        if (i < N_NODES) g_offsets[i] = excl;
        if (t == 511) g_bsum[c] = excl + v;
        __syncthreads();                  // warp_sums reuse across chunks
    }
    grid_bar();

    // ===== phase B2: add chunk prefix, fill cursor, reset counts =====
    for (int c = blockIdx.x; c < NCHUNK; c += gridDim.x) {
        if (t < 32) {
            int acc = 0;
            for (int j = t; j < c; j += 32) acc += g_bsum[j];   // <= 4 iters
            #pragma unroll
            for (int d = 16; d > 0; d >>= 1) acc += __shfl_down_sync(0xffffffffu, acc, d);
            if (t == 0) prefix_s = acc;
        }
        __syncthreads();
        int prefix = prefix_s;
        int i = c * 512 + t;
        if (i < N_NODES) {
            int o = g_offsets[i] + prefix;
            g_offsets[i] = o;
            g_cursor[i]  = o;
            g_counts[i]  = 0;             // restore invariant for next replay
        }
        if (c == NCHUNK - 1 && t == 0)
            g_offsets[N_NODES] = prefix + g_bsum[c];
        __syncthreads();
    }
    grid_bar();

    // ===== phase C: scatter src indices into CSR =====
    for (int i = blockIdx.x * 512 + t; i < N_EDGES / 4; i += gsz) {
        int4 s4 = __ldg((const int4*)src + i);
        int4 d4 = __ldg((const int4*)dst + i);
        g_srcidx[atomicAdd(&g_cursor[d4.x], 1)] = s4.x;
        g_srcidx[atomicAdd(&g_cursor[d4.y], 1)] = s4.y;
        g_srcidx[atomicAdd(&g_cursor[d4.z], 1)] = s4.z;
        g_srcidx[atomicAdd(&g_cursor[d4.w], 1)] = s4.w;
    }
    grid_bar();

    // ===== phase D: three GIN layers =====
    for (int l = 0; l < 3; l++) {
        const float* hin  = (l == 0) ? n_feat : (l == 1 ? g_h0 : g_h1);
        float*       hout = (l == 0) ? g_h0   : (l == 1 ? g_h1 : out);
        const float* Wl   = (l == 0) ? W0 : (l == 1 ? W1 : W2);
        const float* bl   = (l == 0) ? b0 : (l == 1 ? b1 : b2);
        const float  ep   = 1.0f + __ldg(eps + l);
        const int activate = (l < 2);

        // load W once per layer per block
        {
            const float4* W4 = (const float4*)Wl;
            float4* Ws4 = (float4*)Ws;
            Ws4[t]       = W4[t];
            Ws4[t + 512] = W4[t + 512];
        }
        __syncthreads();

        const int jg = t & 15;            // 4-column group
        const int ng = t >> 4;            // 2-node group
        float4 bj = *(const float4*)(bl + jg * 4);

        for (int tile = blockIdx.x; tile < NTILES; tile += gridDim.x) {
            int base = tile * 64;

            // ---- aggregation: warp handles 4 nodes, unroll 8 ----
            #pragma unroll
            for (int q = 0; q < 4; q++) {
                int nl = wid * 4 + q;
                int n = base + nl;
                if (n < N_NODES) {
                    int beg = g_offsets[n];
                    int end = g_offsets[n + 1];
                    float m0 = -CUDART_INF_F, m1 = -CUDART_INF_F;
                    int i = beg;
                    for (; i + 8 <= end; i += 8) {
                        int sx[8];
                        #pragma unroll
                        for (int u = 0; u < 8; u++) sx[u] = __ldg(&g_srcidx[i + u]);
                        float2 a[8];
                        #pragma unroll
                        for (int u = 0; u < 8; u++)
                            a[u] = __ldg((const float2*)(hin + (size_t)sx[u] * DIM) + lane);
                        #pragma unroll
                        for (int u = 0; u < 8; u++) {
                            m0 = fmaxf(m0, a[u].x);
                            m1 = fmaxf(m1, a[u].y);
                        }
                    }
                    for (; i < end; ++i) {
                        int s = __ldg(&g_srcidx[i]);
                        float2 a = __ldg((const float2*)(hin + (size_t)s * DIM) + lane);
                        m0 = fmaxf(m0, a.x);
                        m1 = fmaxf(m1, a.y);
                    }
                    if (beg == end) { m0 = 0.0f; m1 = 0.0f; }   // DGL zero-fill
                    float2 hs = __ldg((const float2*)(hin + (size_t)n * DIM) + lane);
                    float2 xv;
                    xv.x = fmaf(ep, hs.x, m0);
                    xv.y = fmaf(ep, hs.y, m1);
                    *(float2*)&Xs[nl * 68 + lane * 2] = xv;
                }
            }
            __syncthreads();

            // ---- GEMM: out[64x64] = Xs @ Ws + b ----
            float acc[2][4];
            #pragma unroll
            for (int i = 0; i < 2; i++) {
                acc[i][0] = bj.x; acc[i][1] = bj.y; acc[i][2] = bj.z; acc[i][3] = bj.w;
            }
            #pragma unroll
            for (int k = 0; k < 64; k++) {
                float4 w = *(const float4*)&Ws[k * 64 + jg * 4];
                float x0 = Xs[(ng * 2 + 0) * 68 + k];
                float x1 = Xs[(ng * 2 + 1) * 68 + k];
                acc[0][0] = fmaf(x0, w.x, acc[0][0]);
                acc[0][1] = fmaf(x0, w.y, acc[0][1]);
                acc[0][2] = fmaf(x0, w.z, acc[0][2]);
                acc[0][3] = fmaf(x0, w.w, acc[0][3]);
                acc[1][0] = fmaf(x1, w.x, acc[1][0]);
                acc[1][1] = fmaf(x1, w.y, acc[1][1]);
                acc[1][2] = fmaf(x1, w.z, acc[1][2]);
                acc[1][3] = fmaf(x1, w.w, acc[1][3]);
            }
            #pragma unroll
            for (int i = 0; i < 2; i++) {
                int n = base + ng * 2 + i;
                if (n < N_NODES) {
                    float4 v;
                    v.x = acc[i][0]; v.y = acc[i][1]; v.z = acc[i][2]; v.w = acc[i][3];
                    if (activate) {
                        v.x = v.x >= 0.f ? v.x : 0.01f * v.x;
                        v.y = v.y >= 0.f ? v.y : 0.01f * v.y;
                        v.z = v.z >= 0.f ? v.z : 0.01f * v.z;
                        v.w = v.w >= 0.f ? v.w : 0.01f * v.w;
                    }
                    *(float4*)&hout[(size_t)n * DIM + jg * 4] = v;
                }
            }
            __syncthreads();              // Xs reuse guard for next tile
        }
        grid_bar();                       // layer l output complete chip-wide
    }
}

// ---------------- launch ----------------
extern "C" void kernel_launch(void* const* d_in, const int* in_sizes, int n_in,
                              void* d_out, int out_size) {
    const float* n_feat = (const float*)d_in[0];
    const float* W0 = (const float*)d_in[1];
    const float* b0 = (const float*)d_in[2];
    const float* W1 = (const float*)d_in[3];
    const float* b1 = (const float*)d_in[4];
    const float* W2 = (const float*)d_in[5];
    const float* b2 = (const float*)d_in[6];
    const float* eps = (const float*)d_in[7];
    const int*   src = (const int*)d_in[8];
    const int*   dst = (const int*)d_in[9];
    float* out = (float*)d_out;

    int dev = 0;
    cudaGetDevice(&dev);
    int nsm = 0;
    cudaDeviceGetAttribute(&nsm, cudaDevAttrMultiProcessorCount, dev);
    int occ = 0;
    cudaOccupancyMaxActiveBlocksPerMultiprocessor(&occ, k_gin_all, 512, 0);
    if (occ < 1) occ = 1;
    int grid = nsm * occ;                 // all blocks co-resident -> barrier safe

    k_gin_all<<<grid, 512>>>(n_feat, W0, b0, W1, b1, W2, b2, eps, src, dst, out);
}

// round 5
// speedup vs baseline: 1.1865x; 1.1865x over previous
#include <cuda_runtime.h>
#include <math_constants.h>

#define N_NODES 50000
#define N_EDGES 800000
#define DIM 64
#define NCHUNK 98          // 98*512 = 50176 >= 50000 ; 98 <= 148 SMs (co-resident)
#define NQ (N_EDGES / 4)   // 200000 int4 groups
#define NHALF (NQ / 2)     // 100000

// ---- device scratch (no allocations allowed; static zero-init) ----
__device__ int   g_counts[N_NODES];      // invariant: zero at entry of every replay
__device__ int   g_offsets[N_NODES + 1];
__device__ int   g_cursor[N_NODES];
__device__ int   g_csum[NCHUNK];
__device__ volatile int g_cflag[NCHUNK]; // invariant: zero at entry (reset by k_scatter)
__device__ int   g_srcidx[N_EDGES];
__device__ float g_h0[N_NODES * DIM];
__device__ float g_h1[N_NODES * DIM];

// ---------------- CSR build ----------------

// 8 edges per thread: two coalesced int4 streams (higher atomic MLP)
__global__ void k_count(const int* __restrict__ dst) {
    int i = blockIdx.x * blockDim.x + threadIdx.x;
    if (i < NHALF) {
        int4 a = __ldg((const int4*)dst + i);
        int4 b = __ldg((const int4*)dst + i + NHALF);
        atomicAdd(&g_counts[a.x], 1);
        atomicAdd(&g_counts[a.y], 1);
        atomicAdd(&g_counts[a.z], 1);
        atomicAdd(&g_counts[a.w], 1);
        atomicAdd(&g_counts[b.x], 1);
        atomicAdd(&g_counts[b.y], 1);
        atomicAdd(&g_counts[b.z], 1);
        atomicAdd(&g_counts[b.w], 1);
    }
}

// single-kernel scan via decoupled lookback (all 98 blocks co-resident)
__global__ void __launch_bounds__(512) k_scan() {
    __shared__ int warp_sums[16];
    __shared__ int prefix_s;
    const int t = threadIdx.x, lane = t & 31, wid = t >> 5;
    const int c = blockIdx.x;
    const int i = c * 512 + t;

    // local 512-wide exclusive scan of counts
    int v = (i < N_NODES) ? g_counts[i] : 0;
    int s = v;
    #pragma unroll
    for (int d = 1; d < 32; d <<= 1) {
        int y = __shfl_up_sync(0xffffffffu, s, d);
        if (lane >= d) s += y;
    }
    if (lane == 31) warp_sums[wid] = s;
    __syncthreads();
    if (wid == 0 && lane < 16) {
        int ws = warp_sums[lane];
        #pragma unroll
        for (int d = 1; d < 16; d <<= 1) {
            int y = __shfl_up_sync(0xffffu, ws, d);
            if (lane >= d) ws += y;
        }
        warp_sums[lane] = ws;
    }
    __syncthreads();
    int excl = s - v + (wid > 0 ? warp_sums[wid - 1] : 0);

    // publish chunk aggregate (warp 15 does this while warp 0 may already spin)
    if (t == 511) {
        g_csum[c] = excl + v;
        __threadfence();
        g_cflag[c] = 1;
    }

    // lookback: sum all predecessor aggregates
    if (t < 32) {
        int acc = 0;
        for (int j = lane; j < c; j += 32) {
            while (g_cflag[j] == 0) { }          // spin; publisher is resident
            acc += *(volatile int*)&g_csum[j];
        }
        #pragma unroll
        for (int d = 16; d > 0; d >>= 1) acc += __shfl_down_sync(0xffffffffu, acc, d);
        if (lane == 0) prefix_s = acc;
    }
    __syncthreads();
    int prefix = prefix_s;

    if (i < N_NODES) {
        int o = excl + prefix;
        g_offsets[i] = o;
        g_cursor[i]  = o;
        g_counts[i]  = 0;                        // restore invariant for next replay
    }
    if (c == NCHUNK - 1 && t == 511)
        g_offsets[N_NODES] = prefix + excl + v;
}

// 8 edges per thread; also resets the scan flags for the next replay
__global__ void k_scatter(const int* __restrict__ src, const int* __restrict__ dst) {
    int i = blockIdx.x * blockDim.x + threadIdx.x;
    if (i < NCHUNK) g_cflag[i] = 0;              // flag reset (invariant)
    if (i < NHALF) {
        int4 sa = __ldg((const int4*)src + i);
        int4 da = __ldg((const int4*)dst + i);
        int4 sb = __ldg((const int4*)src + i + NHALF);
        int4 db = __ldg((const int4*)dst + i + NHALF);
        g_srcidx[atomicAdd(&g_cursor[da.x], 1)] = sa.x;
        g_srcidx[atomicAdd(&g_cursor[da.y], 1)] = sa.y;
        g_srcidx[atomicAdd(&g_cursor[da.z], 1)] = sa.z;
        g_srcidx[atomicAdd(&g_cursor[da.w], 1)] = sa.w;
        g_srcidx[atomicAdd(&g_cursor[db.x], 1)] = sb.x;
        g_srcidx[atomicAdd(&g_cursor[db.y], 1)] = sb.y;
        g_srcidx[atomicAdd(&g_cursor[db.z], 1)] = sb.z;
        g_srcidx[atomicAdd(&g_cursor[db.w], 1)] = sb.w;
    }
}

// ---------------- fused layer: agg (segment-max) + GEMM + bias + leaky-relu ----
__global__ void __launch_bounds__(512) k_layer(
        const float* __restrict__ h,
        const float* __restrict__ W,
        const float* __restrict__ bias,
        const float* __restrict__ eps, int layer,
        float* __restrict__ out, int activate) {
    __shared__ float Ws[64 * 64];     // [k][j]
    __shared__ float Xs[64 * 68];     // padded stride 68

    int t = threadIdx.x;              // 0..511
    int base = blockIdx.x * 64;

    // load W via float4 (1024 float4 over 512 threads)
    const float4* W4 = (const float4*)W;
    float4* Ws4 = (float4*)Ws;
    Ws4[t]       = W4[t];
    Ws4[t + 512] = W4[t + 512];

    float ep = 1.0f + __ldg(eps + layer);
    int warp = t >> 5, lane = t & 31;

    // ---- phase 1: aggregation, warp handles 4 nodes, unroll 8 ----
    #pragma unroll
    for (int q = 0; q < 4; q++) {
        int nl = warp * 4 + q;
        int n = base + nl;
        if (n < N_NODES) {
            int beg = g_offsets[n];
            int end = g_offsets[n + 1];
            float m0 = -CUDART_INF_F, m1 = -CUDART_INF_F;
            int i = beg;
            for (; i + 8 <= end; i += 8) {
                int sx[8];
                #pragma unroll
                for (int u = 0; u < 8; u++) sx[u] = __ldg(&g_srcidx[i + u]);
                float2 a[8];
                #pragma unroll
                for (int u = 0; u < 8; u++)
                    a[u] = __ldg((const float2*)(h + (size_t)sx[u] * DIM) + lane);
                #pragma unroll
                for (int u = 0; u < 8; u++) {
                    m0 = fmaxf(m0, a[u].x);
                    m1 = fmaxf(m1, a[u].y);
                }
            }
            for (; i < end; ++i) {
                int s = __ldg(&g_srcidx[i]);
                float2 a = __ldg((const float2*)(h + (size_t)s * DIM) + lane);
                m0 = fmaxf(m0, a.x);
                m1 = fmaxf(m1, a.y);
            }
            if (beg == end) { m0 = 0.0f; m1 = 0.0f; }   // DGL zero-fill
            float2 hs = __ldg((const float2*)(h + (size_t)n * DIM) + lane);
            float2 xv;
            xv.x = fmaf(ep, hs.x, m0);
            xv.y = fmaf(ep, hs.y, m1);
            *(float2*)&Xs[nl * 68 + lane * 2] = xv;
        }
    }
    __syncthreads();

    // ---- phase 2: GEMM out[64x64] = Xs @ Ws + b ----
    int jg = t & 15;                  // column group (4 cols)
    int ng = t >> 4;                  // node group (2 nodes), 0..31

    float acc[2][4];
    float4 bj = *(const float4*)(bias + jg * 4);
    #pragma unroll
    for (int i = 0; i < 2; i++) {
        acc[i][0] = bj.x; acc[i][1] = bj.y; acc[i][2] = bj.z; acc[i][3] = bj.w;
    }

    #pragma unroll
    for (int k = 0; k < 64; k++) {
        float4 w = *(const float4*)&Ws[k * 64 + jg * 4];
        float x0 = Xs[(ng * 2 + 0) * 68 + k];
        float x1 = Xs[(ng * 2 + 1) * 68 + k];
        acc[0][0] = fmaf(x0, w.x, acc[0][0]);
        acc[0][1] = fmaf(x0, w.y, acc[0][1]);
        acc[0][2] = fmaf(x0, w.z, acc[0][2]);
        acc[0][3] = fmaf(x0, w.w, acc[0][3]);
        acc[1][0] = fmaf(x1, w.x, acc[1][0]);
        acc[1][1] = fmaf(x1, w.y, acc[1][1]);
        acc[1][2] = fmaf(x1, w.z, acc[1][2]);
        acc[1][3] = fmaf(x1, w.w, acc[1][3]);
    }

    #pragma unroll
    for (int i = 0; i < 2; i++) {
        int n = base + ng * 2 + i;
        if (n < N_NODES) {
            float4 v;
            v.x = acc[i][0]; v.y = acc[i][1]; v.z = acc[i][2]; v.w = acc[i][3];
            if (activate) {
                v.x = v.x >= 0.f ? v.x : 0.01f * v.x;
                v.y = v.y >= 0.f ? v.y : 0.01f * v.y;
                v.z = v.z >= 0.f ? v.z : 0.01f * v.z;
                v.w = v.w >= 0.f ? v.w : 0.01f * v.w;
            }
            *(float4*)&out[(size_t)n * DIM + jg * 4] = v;
        }
    }
}

// ---------------- launch ----------------
extern "C" void kernel_launch(void* const* d_in, const int* in_sizes, int n_in,
                              void* d_out, int out_size) {
    const float* n_feat = (const float*)d_in[0];
    const float* W0 = (const float*)d_in[1];
    const float* b0 = (const float*)d_in[2];
    const float* W1 = (const float*)d_in[3];
    const float* b1 = (const float*)d_in[4];
    const float* W2 = (const float*)d_in[5];
    const float* b2 = (const float*)d_in[6];
    const float* eps = (const float*)d_in[7];
    const int*   src = (const int*)d_in[8];
    const int*   dst = (const int*)d_in[9];
    float* out = (float*)d_out;

    float *h0_ptr, *h1_ptr;
    cudaGetSymbolAddress((void**)&h0_ptr, g_h0);
    cudaGetSymbolAddress((void**)&h1_ptr, g_h1);

    // CSR build (3 launches)
    k_count<<<(NHALF + 255) / 256, 256>>>(dst);
    k_scan<<<NCHUNK, 512>>>();
    k_scatter<<<(NHALF + 255) / 256, 256>>>(src, dst);

    const int layer_blocks = (N_NODES + 63) / 64;   // 782

    k_layer<<<layer_blocks, 512>>>(n_feat, W0, b0, eps, 0, h0_ptr, 1);
    k_layer<<<layer_blocks, 512>>>(h0_ptr, W1, b1, eps, 1, h1_ptr, 1);
    k_layer<<<layer_blocks, 512>>>(h1_ptr, W2, b2, eps, 2, out, 0);
}